// round 1
// baseline (speedup 1.0000x reference)
#include <cuda_runtime.h>
#include <cuda_bf16.h>
#include <cstdint>

#define NN    100000
#define RR    7
#define DD    64
#define EDIM  16
#define KTOT  512              // 448 (U) + 64 (x)

// Scratch: per-(node,relation) aggregated messages, [N, R*D] contiguous per node.
__device__ float  g_U[(size_t)NN * RR * DD];        // 179.2 MB
// Combined transposed weights, packed: g_Wc[kk*64 + col] holds W[col][4kk..4kk+3]
__device__ float4 g_Wc[(KTOT / 4) * DD];            // 128 KB
__device__ float  g_bias[DD];

// ---------------------------------------------------------------------------
// K0: build combined transposed weight + bias
// ---------------------------------------------------------------------------
__global__ void prep_kernel(const float* __restrict__ W_lin,  const float* __restrict__ b_lin,
                            const float* __restrict__ W_self, const float* __restrict__ b_self) {
    int tid = blockIdx.x * blockDim.x + threadIdx.x;
    int total = (KTOT / 4) * DD;
    for (int idx = tid; idx < total; idx += gridDim.x * blockDim.x) {
        int kk  = idx / DD;
        int col = idx % DD;
        float t[4];
#pragma unroll
        for (int s = 0; s < 4; s++) {
            int k = kk * 4 + s;
            t[s] = (k < RR * DD) ? W_lin[col * (RR * DD) + k]
                                 : W_self[col * DD + (k - RR * DD)];
        }
        g_Wc[idx] = make_float4(t[0], t[1], t[2], t[3]);
    }
    if (tid < DD) g_bias[tid] = b_lin[tid] + b_self[tid];
}

// ---------------------------------------------------------------------------
// K1: zero the U scratch
// ---------------------------------------------------------------------------
__global__ void zero_kernel() {
    size_t idx = (size_t)blockIdx.x * blockDim.x + threadIdx.x;
    size_t n4  = (size_t)NN * RR * DD / 4;
    if (idx < n4) reinterpret_cast<float4*>(g_U)[idx] = make_float4(0.f, 0.f, 0.f, 0.f);
}

// ---------------------------------------------------------------------------
// K2: edge scatter. 16 threads per edge; thread t owns output dims [4t, 4t+4).
//     msg = w_e * (x[src] + W_edge @ ef + b_edge), vector-atomicAdd into U[seg].
// ---------------------------------------------------------------------------
__global__ void edge_kernel(const float* __restrict__ x,
                            const int*   __restrict__ edge_list,
                            const float* __restrict__ ew,
                            const float* __restrict__ ef,
                            const float* __restrict__ W_edge,
                            const float* __restrict__ b_edge,
                            int E) {
    // We_sh[d*16 + t] = W_edge rows 4t..4t+3, input dim d (transposed for conflict-free LDS)
    __shared__ float4 We_sh[EDIM * 16];
    __shared__ float4 be_sh[16];

    int tid = threadIdx.x;
    {
        int d = tid / 16, t = tid % 16;
        float4 v;
        v.x = W_edge[(4 * t + 0) * EDIM + d];
        v.y = W_edge[(4 * t + 1) * EDIM + d];
        v.z = W_edge[(4 * t + 2) * EDIM + d];
        v.w = W_edge[(4 * t + 3) * EDIM + d];
        We_sh[tid] = v;
        if (tid < 16) be_sh[tid] = reinterpret_cast<const float4*>(b_edge)[tid];
    }
    __syncthreads();

    int e = blockIdx.x * 16 + (tid >> 4);
    int t = tid & 15;
    if (e >= E) return;

    int ni  = edge_list[3 * e + 0];
    int no  = edge_list[3 * e + 1];
    int rel = edge_list[3 * e + 2];
    float w = ew[e];

    const float4* efv = reinterpret_cast<const float4*>(ef + (size_t)e * EDIM);
    float4 acc = be_sh[t];
#pragma unroll
    for (int g = 0; g < 4; g++) {
        float4 fg = efv[g];
        float vals[4] = {fg.x, fg.y, fg.z, fg.w};
#pragma unroll
        for (int s = 0; s < 4; s++) {
            float4 wv = We_sh[(4 * g + s) * 16 + t];
            float  fd = vals[s];
            acc.x += wv.x * fd;
            acc.y += wv.y * fd;
            acc.z += wv.z * fd;
            acc.w += wv.w * fd;
        }
    }

    float4 xg = reinterpret_cast<const float4*>(x + (size_t)ni * DD)[t];
    float4 val;
    val.x = w * (xg.x + acc.x);
    val.y = w * (xg.y + acc.y);
    val.z = w * (xg.z + acc.z);
    val.w = w * (xg.w + acc.w);

    float4* dst = reinterpret_cast<float4*>(g_U + ((size_t)no * RR + rel) * DD + 4 * t);
    atomicAdd(dst, val);   // sm_90+: single RED.ADD.F32x4
}

// ---------------------------------------------------------------------------
// K3: per-node GEMV: out[n] = relu(Wc^T @ [U[n]; x[n]] + bias)
//     256 threads = 4 nodes x 64 cols; U+x rows staged in smem.
// ---------------------------------------------------------------------------
__global__ void out_kernel(const float* __restrict__ x, float* __restrict__ out, int Nnodes) {
    __shared__ float4 u_sh[4 * (KTOT / 4)];  // 4 nodes x 128 float4 = 8 KB
    int tid   = threadIdx.x;
    int node0 = blockIdx.x * 4;

    for (int i = tid; i < 4 * (KTOT / 4); i += 256) {
        int nl = i >> 7;           // /128
        int kk = i & 127;
        int n  = node0 + nl;
        float4 v = make_float4(0.f, 0.f, 0.f, 0.f);
        if (n < Nnodes) {
            if (kk < (RR * DD) / 4)
                v = reinterpret_cast<const float4*>(g_U + (size_t)n * (RR * DD))[kk];
            else
                v = reinterpret_cast<const float4*>(x + (size_t)n * DD)[kk - (RR * DD) / 4];
        }
        u_sh[i] = v;
    }
    __syncthreads();

    int nl  = tid >> 6;
    int col = tid & 63;
    int n   = node0 + nl;
    if (n >= Nnodes) return;

    float acc = g_bias[col];
#pragma unroll 8
    for (int kk = 0; kk < KTOT / 4; kk++) {
        float4 uv = u_sh[nl * (KTOT / 4) + kk];
        float4 wv = g_Wc[kk * DD + col];
        acc += uv.x * wv.x + uv.y * wv.y + uv.z * wv.z + uv.w * wv.w;
    }
    out[(size_t)n * DD + col] = fmaxf(acc, 0.f);
}

// ---------------------------------------------------------------------------
extern "C" void kernel_launch(void* const* d_in, const int* in_sizes, int n_in,
                              void* d_out, int out_size) {
    const float* x      = (const float*)d_in[0];
    const int*   elist  = (const int*)  d_in[1];
    const float* ew     = (const float*)d_in[2];
    const float* ef     = (const float*)d_in[3];
    const float* W_lin  = (const float*)d_in[4];
    const float* b_lin  = (const float*)d_in[5];
    const float* W_self = (const float*)d_in[6];
    const float* b_self = (const float*)d_in[7];
    const float* W_edge = (const float*)d_in[8];
    const float* b_edge = (const float*)d_in[9];
    float*       out    = (float*)d_out;

    int E = in_sizes[2];            // edge_weight element count
    int N = in_sizes[0] / DD;       // x element count / D

    prep_kernel<<<32, 256>>>(W_lin, b_lin, W_self, b_self);

    {
        size_t n4 = (size_t)NN * RR * DD / 4;
        int blocks = (int)((n4 + 255) / 256);
        zero_kernel<<<blocks, 256>>>();
    }

    {
        int blocks = (E + 15) / 16;
        edge_kernel<<<blocks, 256>>>(x, elist, ew, ef, W_edge, b_edge, E);
    }

    {
        int blocks = (N + 3) / 4;
        out_kernel<<<blocks, 256>>>(x, out, N);
    }
}

// round 5
// speedup vs baseline: 1.2308x; 1.2308x over previous
#include <cuda_runtime.h>
#include <cuda_bf16.h>
#include <cstdint>

#define NN    100000
#define RR    7
#define DD    64
#define EDIM  16
#define KU    448              // R*D
#define KTOT  512              // 448 (U) + 64 (x)

typedef unsigned long long ull;

// Scratch: per-(node,relation) aggregated messages, row stride 448 per node.
__device__ float g_U[(size_t)NN * KU];              // 179.2 MB
// Combined weights, interleaved for the GEMM: g_Wp[kk][cg][8] where
//   entry (kk, cg, s*4+j) = Wcomb[2*cg+s][4*kk+j],  Wcomb[col][k] = k<448 ? W_lin : W_self
__device__ float g_Wp[128 * 32 * 8];                // 128 KB
__device__ float g_bias[DD];

// ---- f32x2 helpers (sm_103a packed FMA) -----------------------------------
__device__ __forceinline__ ull f2fma(ull a, ull b, ull c) {
    ull d; asm("fma.rn.f32x2 %0, %1, %2, %3;" : "=l"(d) : "l"(a), "l"(b), "l"(c)); return d;
}
__device__ __forceinline__ ull pk2(float w) {
    ull r; asm("mov.b64 %0, {%1, %1};" : "=l"(r) : "f"(w)); return r;
}
__device__ __forceinline__ float2 up2(ull v) {
    float2 r; asm("mov.b64 {%0, %1}, %2;" : "=f"(r.x), "=f"(r.y) : "l"(v)); return r;
}

// ---------------------------------------------------------------------------
// K0: build interleaved combined weight + bias
// ---------------------------------------------------------------------------
__global__ void prep_kernel(const float* __restrict__ W_lin,  const float* __restrict__ b_lin,
                            const float* __restrict__ W_self, const float* __restrict__ b_self) {
    int tid = blockIdx.x * blockDim.x + threadIdx.x;
    const int total = 128 * 32 * 8;
    for (int idx = tid; idx < total; idx += gridDim.x * blockDim.x) {
        int kk  = idx >> 8;           // /256
        int rem = idx & 255;
        int cg  = rem >> 3;
        int r8  = rem & 7;
        int s   = r8 >> 2;
        int j   = r8 & 3;
        int col = 2 * cg + s;
        int k   = 4 * kk + j;
        float v = (k < KU) ? W_lin[col * KU + k]
                           : W_self[col * DD + (k - KU)];
        g_Wp[idx] = v;
    }
    if (tid < DD) g_bias[tid] = b_lin[tid] + b_self[tid];
}

// ---------------------------------------------------------------------------
// K1: zero the U scratch
// ---------------------------------------------------------------------------
__global__ void zero_kernel() {
    size_t idx = (size_t)blockIdx.x * blockDim.x + threadIdx.x;
    size_t n4  = (size_t)NN * KU / 4;
    if (idx < n4) reinterpret_cast<float4*>(g_U)[idx] = make_float4(0.f, 0.f, 0.f, 0.f);
}

// ---------------------------------------------------------------------------
// K2: edge scatter. 16 threads per edge; thread t owns output dims [4t, 4t+4).
//     msg = w_e * (x[src] + W_edge @ ef + b_edge), vector-atomicAdd into U[seg].
// ---------------------------------------------------------------------------
__global__ void edge_kernel(const float* __restrict__ x,
                            const int*   __restrict__ edge_list,
                            const float* __restrict__ ew,
                            const float* __restrict__ ef,
                            const float* __restrict__ W_edge,
                            const float* __restrict__ b_edge,
                            int E) {
    __shared__ float4 We_sh[EDIM * 16];
    __shared__ float4 be_sh[16];

    int tid = threadIdx.x;
    {
        int d = tid / 16, t = tid % 16;
        float4 v;
        v.x = W_edge[(4 * t + 0) * EDIM + d];
        v.y = W_edge[(4 * t + 1) * EDIM + d];
        v.z = W_edge[(4 * t + 2) * EDIM + d];
        v.w = W_edge[(4 * t + 3) * EDIM + d];
        We_sh[tid] = v;
        if (tid < 16) be_sh[tid] = reinterpret_cast<const float4*>(b_edge)[tid];
    }
    __syncthreads();

    int e = blockIdx.x * 16 + (tid >> 4);
    int t = tid & 15;
    if (e >= E) return;

    int ni  = edge_list[3 * e + 0];
    int no  = edge_list[3 * e + 1];
    int rel = edge_list[3 * e + 2];
    float w = ew[e];

    const float4* efv = reinterpret_cast<const float4*>(ef + (size_t)e * EDIM);
    float4 acc = be_sh[t];
#pragma unroll
    for (int g = 0; g < 4; g++) {
        float4 fg = efv[g];
        float vals[4] = {fg.x, fg.y, fg.z, fg.w};
#pragma unroll
        for (int s = 0; s < 4; s++) {
            float4 wv = We_sh[(4 * g + s) * 16 + t];
            float  fd = vals[s];
            acc.x += wv.x * fd;
            acc.y += wv.y * fd;
            acc.z += wv.z * fd;
            acc.w += wv.w * fd;
        }
    }

    float4 xg = reinterpret_cast<const float4*>(x + (size_t)ni * DD)[t];
    float4 val;
    val.x = w * (xg.x + acc.x);
    val.y = w * (xg.y + acc.y);
    val.z = w * (xg.z + acc.z);
    val.w = w * (xg.w + acc.w);

    float4* dst = reinterpret_cast<float4*>(g_U + ((size_t)no * RR + rel) * DD + 4 * t);
    atomicAdd(dst, val);
}

// ---------------------------------------------------------------------------
// K3: register-blocked GEMM with packed f32x2 FMA.
//     out = relu([U‖x](N x 512) @ Wc(512 x 64) + bias)
//     Block: 32 nodes (16 pairs (p, p+16)), 128 threads.
//     Thread (cg = t&31, g = t>>5): cols {2cg, 2cg+1} x pairs {4g..4g+3}.
// ---------------------------------------------------------------------------
__global__ __launch_bounds__(128) void out_kernel(const float* __restrict__ x,
                                                  float* __restrict__ out, int Nn) {
    extern __shared__ ull u2[];   // 16 pairs x 512 k, each entry = (val(n=p), val(n=p+16))
    int tid  = threadIdx.x;
    int base = blockIdx.x * 32;

    // ---- stage inputs pre-packed as float2 (lane-consecutive k: conflict-free) ----
#pragma unroll
    for (int it = 0; it < 64; it++) {
        int idx = it * 128 + tid;
        int p   = idx >> 9;
        int k   = idx & 511;
        int na  = base + p;
        int nb  = na + 16;
        float a = 0.f, b = 0.f;
        if (k < KU) {
            if (na < Nn) a = g_U[(size_t)na * KU + k];
            if (nb < Nn) b = g_U[(size_t)nb * KU + k];
        } else {
            int kx = k - KU;
            if (na < Nn) a = x[(size_t)na * DD + kx];
            if (nb < Nn) b = x[(size_t)nb * DD + kx];
        }
        float2 v = make_float2(a, b);
        u2[idx] = *reinterpret_cast<ull*>(&v);
    }
    __syncthreads();

    int cg = tid & 31;
    int g  = tid >> 5;

    float bc0 = g_bias[2 * cg];
    float bc1 = g_bias[2 * cg + 1];
    ull acc[4][2];
#pragma unroll
    for (int q = 0; q < 4; q++) { acc[q][0] = pk2(bc0); acc[q][1] = pk2(bc1); }

#pragma unroll 2
    for (int kk = 0; kk < 128; kk++) {
        const float4* wrow = reinterpret_cast<const float4*>(g_Wp + kk * 256 + cg * 8);
        float4 wa = __ldg(wrow);       // col 2cg,   k = 4kk..4kk+3
        float4 wb = __ldg(wrow + 1);   // col 2cg+1
        ull wA0 = pk2(wa.x), wA1 = pk2(wa.y), wA2 = pk2(wa.z), wA3 = pk2(wa.w);
        ull wB0 = pk2(wb.x), wB1 = pk2(wb.y), wB2 = pk2(wb.z), wB3 = pk2(wb.w);
#pragma unroll
        for (int q = 0; q < 4; q++) {
            const ull* up = &u2[(g * 4 + q) * 512 + 4 * kk];
            ull i0 = up[0], i1 = up[1], i2 = up[2], i3 = up[3];
            acc[q][0] = f2fma(wA0, i0, acc[q][0]);
            acc[q][1] = f2fma(wB0, i0, acc[q][1]);
            acc[q][0] = f2fma(wA1, i1, acc[q][0]);
            acc[q][1] = f2fma(wB1, i1, acc[q][1]);
            acc[q][0] = f2fma(wA2, i2, acc[q][0]);
            acc[q][1] = f2fma(wB2, i2, acc[q][1]);
            acc[q][0] = f2fma(wA3, i3, acc[q][0]);
            acc[q][1] = f2fma(wB3, i3, acc[q][1]);
        }
    }

    // ---- epilogue: relu + coalesced STG.64 (cols 2cg,2cg+1 adjacent) ----
#pragma unroll
    for (int q = 0; q < 4; q++) {
        float2 a0 = up2(acc[q][0]);   // (col c0, node p), (col c0, node p+16)
        float2 a1 = up2(acc[q][1]);   // (col c1, ...)
        int p = g * 4 + q;
        int n0 = base + p;
        int n1 = n0 + 16;
        if (n0 < Nn) {
            float2 o = make_float2(fmaxf(a0.x, 0.f), fmaxf(a1.x, 0.f));
            *reinterpret_cast<float2*>(out + (size_t)n0 * DD + 2 * cg) = o;
        }
        if (n1 < Nn) {
            float2 o = make_float2(fmaxf(a0.y, 0.f), fmaxf(a1.y, 0.f));
            *reinterpret_cast<float2*>(out + (size_t)n1 * DD + 2 * cg) = o;
        }
    }
}

// ---------------------------------------------------------------------------
extern "C" void kernel_launch(void* const* d_in, const int* in_sizes, int n_in,
                              void* d_out, int out_size) {
    const float* x      = (const float*)d_in[0];
    const int*   elist  = (const int*)  d_in[1];
    const float* ew     = (const float*)d_in[2];
    const float* ef     = (const float*)d_in[3];
    const float* W_lin  = (const float*)d_in[4];
    const float* b_lin  = (const float*)d_in[5];
    const float* W_self = (const float*)d_in[6];
    const float* b_self = (const float*)d_in[7];
    const float* W_edge = (const float*)d_in[8];
    const float* b_edge = (const float*)d_in[9];
    float*       out    = (float*)d_out;

    int E = in_sizes[2];            // edge_weight element count
    int N = in_sizes[0] / DD;       // x element count / D

    static bool attr_set = false;
    if (!attr_set) {
        cudaFuncSetAttribute(out_kernel, cudaFuncAttributeMaxDynamicSharedMemorySize, 65536);
        attr_set = true;
    }

    prep_kernel<<<64, 256>>>(W_lin, b_lin, W_self, b_self);

    {
        size_t n4 = (size_t)NN * KU / 4;
        int blocks = (int)((n4 + 255) / 256);
        zero_kernel<<<blocks, 256>>>();
    }

    {
        int blocks = (E + 15) / 16;
        edge_kernel<<<blocks, 256>>>(x, elist, ew, ef, W_edge, b_edge, E);
    }

    {
        int blocks = (N + 31) / 32;
        out_kernel<<<blocks, 128, 65536>>>(x, out, N);
    }
}

// round 7
// speedup vs baseline: 1.2479x; 1.0139x over previous
#include <cuda_runtime.h>
#include <cuda_bf16.h>
#include <cstdint>

#define NN    100000
#define RR    7
#define DD    64
#define EDIM  16
#define KU    448              // R*D
#define KTOT  512              // 448 (U) + 64 (x)

typedef unsigned long long ull;

// Scratch: per-(node,relation) aggregated messages, row stride 448 per node.
__device__ float g_U[(size_t)NN * KU];              // 179.2 MB
// Combined weights, interleaved for the GEMM: g_Wp[kk][cg][8] where
//   entry (kk, cg, s*4+j) = Wcomb[2*cg+s][4*kk+j],  Wcomb[col][k] = k<448 ? W_lin : W_self
__device__ float g_Wp[128 * 32 * 8];                // 128 KB
__device__ float g_bias[DD];

// ---- f32x2 helpers (sm_103a packed FMA) -----------------------------------
__device__ __forceinline__ ull f2fma(ull a, ull b, ull c) {
    ull d; asm("fma.rn.f32x2 %0, %1, %2, %3;" : "=l"(d) : "l"(a), "l"(b), "l"(c)); return d;
}
__device__ __forceinline__ ull pk2(float w) {
    ull r; asm("mov.b64 %0, {%1, %1};" : "=l"(r) : "f"(w)); return r;
}
__device__ __forceinline__ float2 up2(ull v) {
    float2 r; asm("mov.b64 {%0, %1}, %2;" : "=f"(r.x), "=f"(r.y) : "l"(v)); return r;
}

// ---------------------------------------------------------------------------
// K0: build interleaved combined weight + bias
// ---------------------------------------------------------------------------
__global__ void prep_kernel(const float* __restrict__ W_lin,  const float* __restrict__ b_lin,
                            const float* __restrict__ W_self, const float* __restrict__ b_self) {
    int tid = blockIdx.x * blockDim.x + threadIdx.x;
    const int total = 128 * 32 * 8;
    for (int idx = tid; idx < total; idx += gridDim.x * blockDim.x) {
        int kk  = idx >> 8;           // /256
        int rem = idx & 255;
        int cg  = rem >> 3;
        int r8  = rem & 7;
        int s   = r8 >> 2;
        int j   = r8 & 3;
        int col = 2 * cg + s;
        int k   = 4 * kk + j;
        float v = (k < KU) ? W_lin[col * KU + k]
                           : W_self[col * DD + (k - KU)];
        g_Wp[idx] = v;
    }
    if (tid < DD) g_bias[tid] = b_lin[tid] + b_self[tid];
}

// ---------------------------------------------------------------------------
// K1: zero the U scratch
// ---------------------------------------------------------------------------
__global__ void zero_kernel() {
    size_t idx = (size_t)blockIdx.x * blockDim.x + threadIdx.x;
    size_t n4  = (size_t)NN * KU / 4;
    if (idx < n4) reinterpret_cast<float4*>(g_U)[idx] = make_float4(0.f, 0.f, 0.f, 0.f);
}

// ---------------------------------------------------------------------------
// K2: edge scatter. 16 threads per edge; thread t owns output dims [4t, 4t+4).
//     msg = w_e * (x[src] + W_edge @ ef + b_edge), vector-atomicAdd into U[seg].
// ---------------------------------------------------------------------------
__global__ void edge_kernel(const float* __restrict__ x,
                            const int*   __restrict__ edge_list,
                            const float* __restrict__ ew,
                            const float* __restrict__ ef,
                            const float* __restrict__ W_edge,
                            const float* __restrict__ b_edge,
                            int E) {
    __shared__ float4 We_sh[EDIM * 16];
    __shared__ float4 be_sh[16];

    int tid = threadIdx.x;
    {
        int d = tid / 16, t = tid % 16;
        float4 v;
        v.x = W_edge[(4 * t + 0) * EDIM + d];
        v.y = W_edge[(4 * t + 1) * EDIM + d];
        v.z = W_edge[(4 * t + 2) * EDIM + d];
        v.w = W_edge[(4 * t + 3) * EDIM + d];
        We_sh[tid] = v;
        if (tid < 16) be_sh[tid] = reinterpret_cast<const float4*>(b_edge)[tid];
    }
    __syncthreads();

    int e = blockIdx.x * 16 + (tid >> 4);
    int t = tid & 15;
    if (e >= E) return;

    int ni  = edge_list[3 * e + 0];
    int no  = edge_list[3 * e + 1];
    int rel = edge_list[3 * e + 2];
    float w = ew[e];

    const float4* efv = reinterpret_cast<const float4*>(ef + (size_t)e * EDIM);
    float4 acc = be_sh[t];
#pragma unroll
    for (int g = 0; g < 4; g++) {
        float4 fg = efv[g];
        float vals[4] = {fg.x, fg.y, fg.z, fg.w};
#pragma unroll
        for (int s = 0; s < 4; s++) {
            float4 wv = We_sh[(4 * g + s) * 16 + t];
            float  fd = vals[s];
            acc.x += wv.x * fd;
            acc.y += wv.y * fd;
            acc.z += wv.z * fd;
            acc.w += wv.w * fd;
        }
    }

    float4 xg = reinterpret_cast<const float4*>(x + (size_t)ni * DD)[t];
    float4 val;
    val.x = w * (xg.x + acc.x);
    val.y = w * (xg.y + acc.y);
    val.z = w * (xg.z + acc.z);
    val.w = w * (xg.w + acc.w);

    float4* dst = reinterpret_cast<float4*>(g_U + ((size_t)no * RR + rel) * DD + 4 * t);
    atomicAdd(dst, val);
}

// ---------------------------------------------------------------------------
// K3: register-blocked GEMM with packed f32x2 FMA, K-split staging (2 x 32KB).
//     out = relu([U‖x](N x 512) @ Wc(512 x 64) + bias)
//     Block: 32 nodes (16 pairs (p, p+16)), 128 threads, 32KB static smem.
//     Thread (cg = t&31, g = t>>5): cols {2cg, 2cg+1} x pairs {4g..4g+3}.
// ---------------------------------------------------------------------------
__global__ __launch_bounds__(128) void out_kernel(const float* __restrict__ x,
                                                  float* __restrict__ out, int Nn) {
    __shared__ ull u2[16 * 256];   // 16 pairs x 256 k-slice, (val(p), val(p+16)) packed
    int tid  = threadIdx.x;
    int base = blockIdx.x * 32;

    int cg = tid & 31;
    int g  = tid >> 5;

    float bc0 = g_bias[2 * cg];
    float bc1 = g_bias[2 * cg + 1];
    ull acc[4][2];
#pragma unroll
    for (int q = 0; q < 4; q++) { acc[q][0] = pk2(bc0); acc[q][1] = pk2(bc1); }

#pragma unroll
    for (int h = 0; h < 2; h++) {
        if (h) __syncthreads();    // protect smem reuse across halves

        // ---- stage k in [h*256, h*256+256), pre-packed float2, coalesced ----
#pragma unroll
        for (int it = 0; it < 32; it++) {
            int idx = it * 128 + tid;
            int p   = idx >> 8;            // pair 0..15
            int k   = (idx & 255) + h * 256;
            int na  = base + p;
            int nb  = na + 16;
            float a = 0.f, b = 0.f;
            if (k < KU) {
                if (na < Nn) a = g_U[(size_t)na * KU + k];
                if (nb < Nn) b = g_U[(size_t)nb * KU + k];
            } else {
                int kx = k - KU;
                if (na < Nn) a = x[(size_t)na * DD + kx];
                if (nb < Nn) b = x[(size_t)nb * DD + kx];
            }
            float2 v = make_float2(a, b);
            u2[idx] = *reinterpret_cast<ull*>(&v);
        }
        __syncthreads();

        // ---- compute on this K-slice ----
#pragma unroll 2
        for (int kk = 0; kk < 64; kk++) {
            int kg = h * 64 + kk;
            const float4* wrow = reinterpret_cast<const float4*>(g_Wp + kg * 256 + cg * 8);
            float4 wa = __ldg(wrow);       // col 2cg,   k = 4kg..4kg+3
            float4 wb = __ldg(wrow + 1);   // col 2cg+1
            ull wA0 = pk2(wa.x), wA1 = pk2(wa.y), wA2 = pk2(wa.z), wA3 = pk2(wa.w);
            ull wB0 = pk2(wb.x), wB1 = pk2(wb.y), wB2 = pk2(wb.z), wB3 = pk2(wb.w);
#pragma unroll
            for (int q = 0; q < 4; q++) {
                const ull* up = &u2[(g * 4 + q) * 256 + 4 * kk];
                ull i0 = up[0], i1 = up[1], i2 = up[2], i3 = up[3];
                acc[q][0] = f2fma(wA0, i0, acc[q][0]);
                acc[q][1] = f2fma(wB0, i0, acc[q][1]);
                acc[q][0] = f2fma(wA1, i1, acc[q][0]);
                acc[q][1] = f2fma(wB1, i1, acc[q][1]);
                acc[q][0] = f2fma(wA2, i2, acc[q][0]);
                acc[q][1] = f2fma(wB2, i2, acc[q][1]);
                acc[q][0] = f2fma(wA3, i3, acc[q][0]);
                acc[q][1] = f2fma(wB3, i3, acc[q][1]);
            }
        }
    }

    // ---- epilogue: relu + coalesced STG.64 (cols 2cg,2cg+1 adjacent) ----
#pragma unroll
    for (int q = 0; q < 4; q++) {
        float2 a0 = up2(acc[q][0]);   // (col c0, node p), (col c0, node p+16)
        float2 a1 = up2(acc[q][1]);   // (col c1, ...)
        int p = g * 4 + q;
        int n0 = base + p;
        int n1 = n0 + 16;
        if (n0 < Nn) {
            float2 o = make_float2(fmaxf(a0.x, 0.f), fmaxf(a1.x, 0.f));
            *reinterpret_cast<float2*>(out + (size_t)n0 * DD + 2 * cg) = o;
        }
        if (n1 < Nn) {
            float2 o = make_float2(fmaxf(a0.y, 0.f), fmaxf(a1.y, 0.f));
            *reinterpret_cast<float2*>(out + (size_t)n1 * DD + 2 * cg) = o;
        }
    }
}

// ---------------------------------------------------------------------------
extern "C" void kernel_launch(void* const* d_in, const int* in_sizes, int n_in,
                              void* d_out, int out_size) {
    const float* x      = (const float*)d_in[0];
    const int*   elist  = (const int*)  d_in[1];
    const float* ew     = (const float*)d_in[2];
    const float* ef     = (const float*)d_in[3];
    const float* W_lin  = (const float*)d_in[4];
    const float* b_lin  = (const float*)d_in[5];
    const float* W_self = (const float*)d_in[6];
    const float* b_self = (const float*)d_in[7];
    const float* W_edge = (const float*)d_in[8];
    const float* b_edge = (const float*)d_in[9];
    float*       out    = (float*)d_out;

    int E = in_sizes[2];            // edge_weight element count
    int N = in_sizes[0] / DD;       // x element count / D

    prep_kernel<<<64, 256>>>(W_lin, b_lin, W_self, b_self);

    {
        size_t n4 = (size_t)NN * KU / 4;
        int blocks = (int)((n4 + 255) / 256);
        zero_kernel<<<blocks, 256>>>();
    }

    {
        int blocks = (E + 15) / 16;
        edge_kernel<<<blocks, 256>>>(x, elist, ew, ef, W_edge, b_edge, E);
    }

    {
        int blocks = (N + 31) / 32;
        out_kernel<<<blocks, 128>>>(x, out, N);
    }
}